// round 15
// baseline (speedup 1.0000x reference)
#include <cuda_runtime.h>
#include <math.h>

#define SW 21
#define PAD 10
#define IMH 256
#define IMW 256
#define PW 276            // 256 + 2*PAD
#define HW (IMH*IMW)
#define RSTRIP 8
#define NSTRIP (IMH / RSTRIP)   // 32
#define NGROUP 21
#define NT 288            // 9 warps: t<256 outputs, warp 8 covers CS cols 256..275
#define NROWS 28          // RSTRIP + 2*PAD window rows per strip

// -------- scratch (no cudaMalloc allowed) --------
__device__ float g_ypad[PW * PW];          // reflect-padded luminance of clipped rgb
__device__ float g_rgbpad[3][PW * PW];     // reflect-padded raw rgb
__device__ float g_acc[NGROUP][4][HW];     // per-dy-group partial (numR,numG,numB,den)

// reflect index for np.pad(mode='reflect'): -1 -> 1, 256 -> 254
__device__ __forceinline__ int refl(int i) {
    i = (i < 0) ? -i : i;
    return (i > 255) ? (510 - i) : i;
}

// -------- kernel 1: build padded luminance + padded rgb --------
__global__ void prep_kernel(const float* __restrict__ rgb) {
    int idx = blockIdx.x * blockDim.x + threadIdx.x;
    if (idx >= PW * PW) return;
    int I = idx / PW;
    int J = idx - I * PW;
    int p = refl(I - PAD) * IMW + refl(J - PAD);
    float r = rgb[p];
    float g = rgb[HW + p];
    float b = rgb[2 * HW + p];
    g_rgbpad[0][idx] = r;
    g_rgbpad[1][idx] = g;
    g_rgbpad[2][idx] = b;
    float rc = fminf(fmaxf(r, 0.f), 1.f);
    float gc = fminf(fmaxf(g, 0.f), 1.f);
    float bc = fminf(fmaxf(b, 0.f), 1.f);
    g_ypad[idx] = 0.299f * rc + 0.587f * gc + 0.114f * bc;
}

// -------- kernel 2: main NLM. grid = (NSTRIP, NGROUP), block = NT --------
// CTA (s, g): output rows [s*8, s*8+8), dy = g-10, loops dx = -10..10.
// Phase A (t<276): build CS column t. A-stream in regs; B-stream TRANSPOSED in SMEM
//   (s_yBt[col][28]) so the 28 row-values load as 7 conflict-free LDS.128.
// Phase B (t<256): ty=t&7 row, tx=t>>3 -> 8-col segment; conflict-free LDS.128.
__global__ void __launch_bounds__(NT, 2) nlm_kernel(const float* __restrict__ hparam) {
    __shared__ float s_yBt[PW * NROWS];       // TRANSPOSED dy-shifted rows: [col][row]
    __shared__ float s_cs[2][RSTRIP * PW];    // double-buffered per-row column sums

    const int t  = threadIdx.x;
    const int h0 = blockIdx.x * RSTRIP;
    const int dy = (int)blockIdx.y - PAD;

    const float hr    = fmaxf(hparam[0], 0.f) + 1e-8f;
    const float inv_h = 1.0f / hr;
    const float dmax  = (34.0f * hr) * (34.0f * hr);   // weight <= e^-34 below -> skip

    const bool colA = (t < PW);
    const int  cA   = colA ? (refl(t - PAD) + PAD) : PAD;   // A column, hoisted
    const bool outA = (t < IMW);
    const int  ty   = t & 7;           // output row within strip (phase B)
    const int  tx   = t >> 3;          // 8-col segment id
    const int  w0   = tx * 8;

    // ---- stage B rows (transposed) to SMEM; hoist A column to registers ----
    float yA[NROWS];
    if (colA) {
#pragma unroll
        for (int rr = 0; rr < NROWS; rr++) {
            int rA = refl(h0 - PAD + rr) + PAD;                  // ypad row, in [10,265]
            s_yBt[t * NROWS + rr] = g_ypad[(rA + dy) * PW + t];  // rA+dy in [0,275]
            yA[rr] = g_ypad[rA * PW + cA];
        }
    }
    __syncthreads();

    float accR[8], accG[8], accB[8], accD[8];
#pragma unroll
    for (int i = 0; i < 8; i++) { accR[i] = 0.f; accG[i] = 0.f; accB[i] = 0.f; accD[i] = 0.f; }

    const int orow  = h0 + ty;                       // output row (phase B)
    const int rbase = (orow + dy + PAD) * PW;        // + (col+dx+PAD) later

#pragma unroll 2
    for (int dxi = 0; dxi < SW; dxi++) {
        const int dx = dxi - PAD;
        float* cs = s_cs[dxi & 1];

        // ---- phase A: 7 wide loads, batched d^2, tree base sum, short slide ----
        if (colA) {
            const float4* pB4 = (const float4*)(s_yBt + (cA + dx) * NROWS);  // 112B stride: conflict-free
            float d2[NROWS];
#pragma unroll
            for (int q = 0; q < 7; q++) {
                float4 v = pB4[q];
                float da = yA[4 * q + 0] - v.x;
                float db = yA[4 * q + 1] - v.y;
                float dc = yA[4 * q + 2] - v.z;
                float dd = yA[4 * q + 3] - v.w;
                d2[4 * q + 0] = da * da;
                d2[4 * q + 1] = db * db;
                d2[4 * q + 2] = dc * dc;
                d2[4 * q + 3] = dd * dd;
            }
            // tree sum of d2[0..20]  (short dependency depth)
            float s1 = (d2[0] + d2[1]) + (d2[2] + d2[3]);
            float s2 = (d2[4] + d2[5]) + (d2[6] + d2[7]);
            float s3 = (d2[8] + d2[9]) + (d2[10] + d2[11]);
            float s4 = (d2[12] + d2[13]) + (d2[14] + d2[15]);
            float s5 = (d2[16] + d2[17]) + (d2[18] + d2[19]);
            float csum = ((s1 + s2) + (s3 + s4)) + (s5 + d2[20]);
            cs[t] = csum;
#pragma unroll
            for (int k = 1; k < 8; k++) {
                csum += d2[20 + k] - d2[k - 1];
                cs[k * PW + t] = csum;
            }
        }
        __syncthreads();   // orders A(i) writes before B(i) reads; parity protects B(i-1) vs A(i+1)

        // ---- phase B: horizontal sliding 21-sum over 8 outputs ----
        if (outA) {
            const float4* row4 = (const float4*)(cs + ty * PW) + tx * 2;  // conflict-free
            float a[28];
#pragma unroll
            for (int q = 0; q < 7; q++) {
                float4 v = row4[q];
                a[4 * q + 0] = v.x; a[4 * q + 1] = v.y;
                a[4 * q + 2] = v.z; a[4 * q + 3] = v.w;
            }
            float s1 = (a[0] + a[1]) + (a[2] + a[3]);
            float s2 = (a[4] + a[5]) + (a[6] + a[7]);
            float s3 = (a[8] + a[9]) + (a[10] + a[11]);
            float s4 = (a[12] + a[13]) + (a[14] + a[15]);
            float s5 = (a[16] + a[17]) + (a[18] + a[19]);
            float D  = ((s1 + s2) + (s3 + s4)) + (s5 + a[20]);

#pragma unroll
            for (int k = 0; k < 8; k++) {
                if (D < dmax) {
                    float Dc  = fmaxf(D, 0.f);
                    float wgt = expf(-sqrtf(Dc) * inv_h);
                    int rp = rbase + (w0 + k + dx + PAD);
                    accR[k] = fmaf(wgt, g_rgbpad[0][rp], accR[k]);
                    accG[k] = fmaf(wgt, g_rgbpad[1][rp], accG[k]);
                    accB[k] = fmaf(wgt, g_rgbpad[2][rp], accB[k]);
                    accD[k] += wgt;
                }
                if (k < 7) D += a[k + 21] - a[k];
            }
        }
        // no trailing barrier: next iteration writes the other cs buffer
    }

    // ---- exclusive writeout of this (strip, group) slice ----
    if (outA) {
        const int g = blockIdx.y;
        int p = orow * IMW + w0;
        *(float4*)&g_acc[g][0][p]     = make_float4(accR[0], accR[1], accR[2], accR[3]);
        *(float4*)&g_acc[g][0][p + 4] = make_float4(accR[4], accR[5], accR[6], accR[7]);
        *(float4*)&g_acc[g][1][p]     = make_float4(accG[0], accG[1], accG[2], accG[3]);
        *(float4*)&g_acc[g][1][p + 4] = make_float4(accG[4], accG[5], accG[6], accG[7]);
        *(float4*)&g_acc[g][2][p]     = make_float4(accB[0], accB[1], accB[2], accB[3]);
        *(float4*)&g_acc[g][2][p + 4] = make_float4(accB[4], accB[5], accB[6], accB[7]);
        *(float4*)&g_acc[g][3][p]     = make_float4(accD[0], accD[1], accD[2], accD[3]);
        *(float4*)&g_acc[g][3][p + 4] = make_float4(accD[4], accD[5], accD[6], accD[7]);
    }
}

// -------- kernel 3: reduce the 21 dy-group partials, normalize, clip (4 px/thread) --------
__global__ void reduce_kernel(float* __restrict__ out) {
    int q = blockIdx.x * blockDim.x + threadIdx.x;   // float4 index
    if (q >= HW / 4) return;
    float4 nr = make_float4(0.f, 0.f, 0.f, 0.f);
    float4 ng = nr, nb = nr, dn = nr;
#pragma unroll
    for (int g = 0; g < NGROUP; g++) {
        float4 v;
        v = ((const float4*)g_acc[g][0])[q]; nr.x += v.x; nr.y += v.y; nr.z += v.z; nr.w += v.w;
        v = ((const float4*)g_acc[g][1])[q]; ng.x += v.x; ng.y += v.y; ng.z += v.z; ng.w += v.w;
        v = ((const float4*)g_acc[g][2])[q]; nb.x += v.x; nb.y += v.y; nb.z += v.z; nb.w += v.w;
        v = ((const float4*)g_acc[g][3])[q]; dn.x += v.x; dn.y += v.y; dn.z += v.z; dn.w += v.w;
    }
    float4 o0, o1, o2;
    o0.x = fminf(fmaxf(nr.x / dn.x, 0.f), 1.f);
    o0.y = fminf(fmaxf(nr.y / dn.y, 0.f), 1.f);
    o0.z = fminf(fmaxf(nr.z / dn.z, 0.f), 1.f);
    o0.w = fminf(fmaxf(nr.w / dn.w, 0.f), 1.f);
    o1.x = fminf(fmaxf(ng.x / dn.x, 0.f), 1.f);
    o1.y = fminf(fmaxf(ng.y / dn.y, 0.f), 1.f);
    o1.z = fminf(fmaxf(ng.z / dn.z, 0.f), 1.f);
    o1.w = fminf(fmaxf(ng.w / dn.w, 0.f), 1.f);
    o2.x = fminf(fmaxf(nb.x / dn.x, 0.f), 1.f);
    o2.y = fminf(fmaxf(nb.y / dn.y, 0.f), 1.f);
    o2.z = fminf(fmaxf(nb.z / dn.z, 0.f), 1.f);
    o2.w = fminf(fmaxf(nb.w / dn.w, 0.f), 1.f);
    ((float4*)out)[q]              = o0;
    ((float4*)(out + HW))[q]       = o1;
    ((float4*)(out + 2 * HW))[q]   = o2;
}

extern "C" void kernel_launch(void* const* d_in, const int* in_sizes, int n_in,
                              void* d_out, int out_size) {
    const float* rgb = (const float*)d_in[0];
    const float* hp  = (const float*)d_in[1];
    if (n_in >= 2 && in_sizes[0] == 1) {   // defensive input-order check
        rgb = (const float*)d_in[1];
        hp  = (const float*)d_in[0];
    }
    prep_kernel<<<(PW * PW + 255) / 256, 256>>>(rgb);
    nlm_kernel<<<dim3(NSTRIP, NGROUP), NT>>>(hp);
    reduce_kernel<<<(HW / 4 + 255) / 256, 256>>>((float*)d_out);
}

// round 16
// speedup vs baseline: 1.0259x; 1.0259x over previous
#include <cuda_runtime.h>
#include <math.h>

#define SW 21
#define PAD 10
#define IMH 256
#define IMW 256
#define PW 276            // 256 + 2*PAD
#define HW (IMH*IMW)
#define RSTRIP 8
#define NSTRIP (IMH / RSTRIP)   // 32
#define NGROUP 21
#define NT 288            // 9 warps: t<256 outputs, warp 8 covers CS cols 256..275
#define NROWS 28          // RSTRIP + 2*PAD window rows per strip
#define NPAIR 11          // ceil(21/2) dx pairs, one barrier each

// -------- scratch (no cudaMalloc allowed) --------
__device__ float  g_ypad[PW * PW];         // reflect-padded luminance of clipped rgb
__device__ float4 g_rgbpad4[PW * PW];      // reflect-padded raw rgb, packed (r,g,b,_)
__device__ float  g_acc[NGROUP][4][HW];    // per-dy-group partial (numR,numG,numB,den)

// reflect index for np.pad(mode='reflect'): -1 -> 1, 256 -> 254
__device__ __forceinline__ int refl(int i) {
    i = (i < 0) ? -i : i;
    return (i > 255) ? (510 - i) : i;
}

// -------- kernel 1: build padded luminance + packed padded rgb --------
__global__ void prep_kernel(const float* __restrict__ rgb) {
    int idx = blockIdx.x * blockDim.x + threadIdx.x;
    if (idx >= PW * PW) return;
    int I = idx / PW;
    int J = idx - I * PW;
    int p = refl(I - PAD) * IMW + refl(J - PAD);
    float r = rgb[p];
    float g = rgb[HW + p];
    float b = rgb[2 * HW + p];
    g_rgbpad4[idx] = make_float4(r, g, b, 0.f);
    float rc = fminf(fmaxf(r, 0.f), 1.f);
    float gc = fminf(fmaxf(g, 0.f), 1.f);
    float bc = fminf(fmaxf(b, 0.f), 1.f);
    g_ypad[idx] = 0.299f * rc + 0.587f * gc + 0.114f * bc;
}

// -------- kernel 2: main NLM. grid = (NSTRIP, NGROUP), block = NT --------
// CTA (s, g): output rows [s*8, s*8+8), dy = g-10. dx processed in PAIRS:
// one barrier per 2 dx (4 CS buffers), doubling independent work per segment.
__global__ void __launch_bounds__(NT, 2) nlm_kernel(const float* __restrict__ hparam) {
    extern __shared__ float sm[];
    float* s_yB = sm;                 // [NROWS][PW] dy-shifted rows (pre-reflected)
    float* s_cs = sm + NROWS * PW;    // [4][RSTRIP][PW] column sums (pair-buffered)

    const int t  = threadIdx.x;
    const int h0 = blockIdx.x * RSTRIP;
    const int dy = (int)blockIdx.y - PAD;

    const float hr    = fmaxf(hparam[0], 0.f) + 1e-8f;
    const float inv_h = 1.0f / hr;
    const float dmax  = (34.0f * hr) * (34.0f * hr);   // weight <= e^-34 below -> skip

    const bool colA = (t < PW);
    const int  cA   = colA ? (refl(t - PAD) + PAD) : PAD;   // A column, hoisted
    const bool outA = (t < IMW);
    const int  ty   = t & 7;           // output row within strip (phase B)
    const int  tx   = t >> 3;          // 8-col segment id
    const int  w0   = tx * 8;

    // ---- stage B rows to SMEM; hoist A column to registers ----
    float yA[NROWS];
    if (colA) {
#pragma unroll
        for (int rr = 0; rr < NROWS; rr++) {
            int rA = refl(h0 - PAD + rr) + PAD;              // ypad row, in [10,265]
            s_yB[rr * PW + t] = g_ypad[(rA + dy) * PW + t];  // rA+dy in [0,275]
            yA[rr] = g_ypad[rA * PW + cA];
        }
    }
    __syncthreads();

    float accR[8], accG[8], accB[8], accD[8];
#pragma unroll
    for (int i = 0; i < 8; i++) { accR[i] = 0.f; accG[i] = 0.f; accB[i] = 0.f; accD[i] = 0.f; }

    const int orow  = h0 + ty;                       // output row (phase B)
    const int rbase = (orow + dy + PAD) * PW;        // + (col+dx+PAD) later

    // phase A: build CS column t for one dx into buffer cs
    auto phaseA = [&](int dx, float* cs) {
        const float* pB = s_yB + cA + dx;            // cA+dx in [0,275]
        float d2[NROWS];
#pragma unroll
        for (int rr = 0; rr < NROWS; rr++) {
            float d = yA[rr] - pB[rr * PW];
            d2[rr] = d * d;
        }
        float s1 = (d2[0] + d2[1]) + (d2[2] + d2[3]);
        float s2 = (d2[4] + d2[5]) + (d2[6] + d2[7]);
        float s3 = (d2[8] + d2[9]) + (d2[10] + d2[11]);
        float s4 = (d2[12] + d2[13]) + (d2[14] + d2[15]);
        float s5 = (d2[16] + d2[17]) + (d2[18] + d2[19]);
        float csum = ((s1 + s2) + (s3 + s4)) + (s5 + d2[20]);
        cs[t] = csum;
#pragma unroll
        for (int k = 1; k < 8; k++) {
            csum += d2[20 + k] - d2[k - 1];
            cs[k * PW + t] = csum;
        }
    };

    // phase B: consume one dx's CS buffer, accumulate 8 outputs
    auto phaseB = [&](int dx, const float* cs) {
        const float4* row4 = (const float4*)(cs + ty * PW) + tx * 2;  // conflict-free
        float a[28];
#pragma unroll
        for (int q = 0; q < 7; q++) {
            float4 v = row4[q];
            a[4 * q + 0] = v.x; a[4 * q + 1] = v.y;
            a[4 * q + 2] = v.z; a[4 * q + 3] = v.w;
        }
        float s1 = (a[0] + a[1]) + (a[2] + a[3]);
        float s2 = (a[4] + a[5]) + (a[6] + a[7]);
        float s3 = (a[8] + a[9]) + (a[10] + a[11]);
        float s4 = (a[12] + a[13]) + (a[14] + a[15]);
        float s5 = (a[16] + a[17]) + (a[18] + a[19]);
        float D  = ((s1 + s2) + (s3 + s4)) + (s5 + a[20]);

#pragma unroll
        for (int k = 0; k < 8; k++) {
            if (D < dmax) {
                float Dc  = fmaxf(D, 0.f);
                float wgt = expf(-sqrtf(Dc) * inv_h);
                float4 c = g_rgbpad4[rbase + (w0 + k + dx + PAD)];
                accR[k] = fmaf(wgt, c.x, accR[k]);
                accG[k] = fmaf(wgt, c.y, accG[k]);
                accB[k] = fmaf(wgt, c.z, accB[k]);
                accD[k] += wgt;
            }
            if (k < 7) D += a[k + 21] - a[k];
        }
    };

#pragma unroll 1
    for (int p = 0; p < NPAIR; p++) {
        const int dx0 = 2 * p - PAD;
        const bool has1 = (2 * p + 1 < SW);
        float* cs0 = s_cs + ((p & 1) * 2 + 0) * (RSTRIP * PW);
        float* cs1 = s_cs + ((p & 1) * 2 + 1) * (RSTRIP * PW);

        if (colA) {
            phaseA(dx0, cs0);
            if (has1) phaseA(dx0 + 1, cs1);
        }
        __syncthreads();   // one barrier per pair; buffer parity protects reads of pair p-1

        if (outA) {
            phaseB(dx0, cs0);
            if (has1) phaseB(dx0 + 1, cs1);
        }
        // no trailing barrier: next pair writes the other two buffers
    }

    // ---- exclusive writeout of this (strip, group) slice ----
    if (outA) {
        const int g = blockIdx.y;
        int p = orow * IMW + w0;
        *(float4*)&g_acc[g][0][p]     = make_float4(accR[0], accR[1], accR[2], accR[3]);
        *(float4*)&g_acc[g][0][p + 4] = make_float4(accR[4], accR[5], accR[6], accR[7]);
        *(float4*)&g_acc[g][1][p]     = make_float4(accG[0], accG[1], accG[2], accG[3]);
        *(float4*)&g_acc[g][1][p + 4] = make_float4(accG[4], accG[5], accG[6], accG[7]);
        *(float4*)&g_acc[g][2][p]     = make_float4(accB[0], accB[1], accB[2], accB[3]);
        *(float4*)&g_acc[g][2][p + 4] = make_float4(accB[4], accB[5], accB[6], accB[7]);
        *(float4*)&g_acc[g][3][p]     = make_float4(accD[0], accD[1], accD[2], accD[3]);
        *(float4*)&g_acc[g][3][p + 4] = make_float4(accD[4], accD[5], accD[6], accD[7]);
    }
}

// -------- kernel 3: reduce the 21 dy-group partials, normalize, clip (4 px/thread) --------
__global__ void reduce_kernel(float* __restrict__ out) {
    int q = blockIdx.x * blockDim.x + threadIdx.x;   // float4 index
    if (q >= HW / 4) return;
    float4 nr = make_float4(0.f, 0.f, 0.f, 0.f);
    float4 ng = nr, nb = nr, dn = nr;
#pragma unroll
    for (int g = 0; g < NGROUP; g++) {
        float4 v;
        v = ((const float4*)g_acc[g][0])[q]; nr.x += v.x; nr.y += v.y; nr.z += v.z; nr.w += v.w;
        v = ((const float4*)g_acc[g][1])[q]; ng.x += v.x; ng.y += v.y; ng.z += v.z; ng.w += v.w;
        v = ((const float4*)g_acc[g][2])[q]; nb.x += v.x; nb.y += v.y; nb.z += v.z; nb.w += v.w;
        v = ((const float4*)g_acc[g][3])[q]; dn.x += v.x; dn.y += v.y; dn.z += v.z; dn.w += v.w;
    }
    float4 o0, o1, o2;
    o0.x = fminf(fmaxf(nr.x / dn.x, 0.f), 1.f);
    o0.y = fminf(fmaxf(nr.y / dn.y, 0.f), 1.f);
    o0.z = fminf(fmaxf(nr.z / dn.z, 0.f), 1.f);
    o0.w = fminf(fmaxf(nr.w / dn.w, 0.f), 1.f);
    o1.x = fminf(fmaxf(ng.x / dn.x, 0.f), 1.f);
    o1.y = fminf(fmaxf(ng.y / dn.y, 0.f), 1.f);
    o1.z = fminf(fmaxf(ng.z / dn.z, 0.f), 1.f);
    o1.w = fminf(fmaxf(ng.w / dn.w, 0.f), 1.f);
    o2.x = fminf(fmaxf(nb.x / dn.x, 0.f), 1.f);
    o2.y = fminf(fmaxf(nb.y / dn.y, 0.f), 1.f);
    o2.z = fminf(fmaxf(nb.z / dn.z, 0.f), 1.f);
    o2.w = fminf(fmaxf(nb.w / dn.w, 0.f), 1.f);
    ((float4*)out)[q]              = o0;
    ((float4*)(out + HW))[q]       = o1;
    ((float4*)(out + 2 * HW))[q]   = o2;
}

extern "C" void kernel_launch(void* const* d_in, const int* in_sizes, int n_in,
                              void* d_out, int out_size) {
    const float* rgb = (const float*)d_in[0];
    const float* hp  = (const float*)d_in[1];
    if (n_in >= 2 && in_sizes[0] == 1) {   // defensive input-order check
        rgb = (const float*)d_in[1];
        hp  = (const float*)d_in[0];
    }
    const int smem_bytes = (NROWS * PW + 4 * RSTRIP * PW) * sizeof(float);  // 66,240 B
    static bool attr_set = false;
    if (!attr_set) {
        cudaFuncSetAttribute(nlm_kernel, cudaFuncAttributeMaxDynamicSharedMemorySize, smem_bytes);
        attr_set = true;
    }
    prep_kernel<<<(PW * PW + 255) / 256, 256>>>(rgb);
    nlm_kernel<<<dim3(NSTRIP, NGROUP), NT, smem_bytes>>>(hp);
    reduce_kernel<<<(HW / 4 + 255) / 256, 256>>>((float*)d_out);
}

// round 17
// speedup vs baseline: 1.2042x; 1.1738x over previous
#include <cuda_runtime.h>
#include <math.h>

#define SW 21
#define PAD 10
#define IMH 256
#define IMW 256
#define PW 276            // 256 + 2*PAD
#define HW (IMH*IMW)
#define RSTRIP 8
#define NSTRIP (IMH / RSTRIP)   // 32
#define NGROUP 21
#define NT 288            // 9 warps: t<256 outputs, warp 8 covers CS cols 256..275
#define NROWS 28          // RSTRIP + 2*PAD window rows per strip
#define NPAIR 11          // ceil(21/2) dx pairs, one barrier each

// -------- scratch (no cudaMalloc allowed) --------
__device__ float  g_ypad[PW * PW];         // reflect-padded luminance of clipped rgb
__device__ float4 g_rgbpad4[PW * PW];      // reflect-padded raw rgb, packed (r,g,b,_)
__device__ float  g_acc[NGROUP][4][HW];    // per-dy-group partial (numR,numG,numB,den)

// reflect index for np.pad(mode='reflect'): -1 -> 1, 256 -> 254
__device__ __forceinline__ int refl(int i) {
    i = (i < 0) ? -i : i;
    return (i > 255) ? (510 - i) : i;
}

// -------- kernel 1: build padded luminance + packed padded rgb --------
__global__ void prep_kernel(const float* __restrict__ rgb) {
    int idx = blockIdx.x * blockDim.x + threadIdx.x;
    if (idx >= PW * PW) return;
    int I = idx / PW;
    int J = idx - I * PW;
    int p = refl(I - PAD) * IMW + refl(J - PAD);
    float r = rgb[p];
    float g = rgb[HW + p];
    float b = rgb[2 * HW + p];
    g_rgbpad4[idx] = make_float4(r, g, b, 0.f);
    float rc = fminf(fmaxf(r, 0.f), 1.f);
    float gc = fminf(fmaxf(g, 0.f), 1.f);
    float bc = fminf(fmaxf(b, 0.f), 1.f);
    g_ypad[idx] = 0.299f * rc + 0.587f * gc + 0.114f * bc;
}

// -------- kernel 2: main NLM. grid = (NSTRIP, NGROUP), block = NT --------
// CTA (s, g): output rows [s*8, s*8+8), dy = g-10. dx processed in PAIRS
// (one barrier / 2 dx, 4 CS buffers). Phase B: slide 8 D values with a running
// min; ONE branch guards the (rare) accumulate block for the whole segment.
__global__ void __launch_bounds__(NT, 2) nlm_kernel(const float* __restrict__ hparam) {
    extern __shared__ float sm[];
    float* s_yB = sm;                 // [NROWS][PW] dy-shifted rows (pre-reflected)
    float* s_cs = sm + NROWS * PW;    // [4][RSTRIP][PW] column sums (pair-buffered)

    const int t  = threadIdx.x;
    const int h0 = blockIdx.x * RSTRIP;
    const int dy = (int)blockIdx.y - PAD;

    const float hr    = fmaxf(hparam[0], 0.f) + 1e-8f;
    const float inv_h = 1.0f / hr;
    const float dmax  = (34.0f * hr) * (34.0f * hr);   // weight <= e^-34 below -> skip

    const bool colA = (t < PW);
    const int  cA   = colA ? (refl(t - PAD) + PAD) : PAD;   // A column, hoisted
    const bool outA = (t < IMW);
    const int  ty   = t & 7;           // output row within strip (phase B)
    const int  tx   = t >> 3;          // 8-col segment id
    const int  w0   = tx * 8;

    // ---- stage B rows to SMEM; hoist A column to registers ----
    float yA[NROWS];
    if (colA) {
#pragma unroll
        for (int rr = 0; rr < NROWS; rr++) {
            int rA = refl(h0 - PAD + rr) + PAD;              // ypad row, in [10,265]
            s_yB[rr * PW + t] = g_ypad[(rA + dy) * PW + t];  // rA+dy in [0,275]
            yA[rr] = g_ypad[rA * PW + cA];
        }
    }
    __syncthreads();

    float accR[8], accG[8], accB[8], accD[8];
#pragma unroll
    for (int i = 0; i < 8; i++) { accR[i] = 0.f; accG[i] = 0.f; accB[i] = 0.f; accD[i] = 0.f; }

    const int orow  = h0 + ty;                       // output row (phase B)
    const int rbase = (orow + dy + PAD) * PW;        // + (col+dx+PAD) later

    // phase A: build CS column t for one dx into buffer cs
    auto phaseA = [&](int dx, float* cs) {
        const float* pB = s_yB + cA + dx;            // cA+dx in [0,275]
        float d2[NROWS];
#pragma unroll
        for (int rr = 0; rr < NROWS; rr++) {
            float d = yA[rr] - pB[rr * PW];
            d2[rr] = d * d;
        }
        float s1 = (d2[0] + d2[1]) + (d2[2] + d2[3]);
        float s2 = (d2[4] + d2[5]) + (d2[6] + d2[7]);
        float s3 = (d2[8] + d2[9]) + (d2[10] + d2[11]);
        float s4 = (d2[12] + d2[13]) + (d2[14] + d2[15]);
        float s5 = (d2[16] + d2[17]) + (d2[18] + d2[19]);
        float csum = ((s1 + s2) + (s3 + s4)) + (s5 + d2[20]);
        cs[t] = csum;
#pragma unroll
        for (int k = 1; k < 8; k++) {
            csum += d2[20 + k] - d2[k - 1];
            cs[k * PW + t] = csum;
        }
    };

    // phase B: slide 8 D values, single rare-branch accumulate
    auto phaseB = [&](int dx, const float* cs) {
        const float4* row4 = (const float4*)(cs + ty * PW) + tx * 2;  // conflict-free
        float a[28];
#pragma unroll
        for (int q = 0; q < 7; q++) {
            float4 v = row4[q];
            a[4 * q + 0] = v.x; a[4 * q + 1] = v.y;
            a[4 * q + 2] = v.z; a[4 * q + 3] = v.w;
        }
        float s1 = (a[0] + a[1]) + (a[2] + a[3]);
        float s2 = (a[4] + a[5]) + (a[6] + a[7]);
        float s3 = (a[8] + a[9]) + (a[10] + a[11]);
        float s4 = (a[12] + a[13]) + (a[14] + a[15]);
        float s5 = (a[16] + a[17]) + (a[18] + a[19]);
        const float D0 = ((s1 + s2) + (s3 + s4)) + (s5 + a[20]);

        // cheap common path: slide + running min, no per-k branches
        float D = D0;
        float m = D0;
#pragma unroll
        for (int k = 1; k < 8; k++) {
            D += a[k + 20] - a[k - 1];
            m = fminf(m, D);
        }

        if (m < dmax) {   // RARE: only segments containing a passing offset
            float Dk = D0;
#pragma unroll
            for (int k = 0; k < 8; k++) {
                if (Dk < dmax) {
                    float Dc  = fmaxf(Dk, 0.f);
                    float wgt = expf(-sqrtf(Dc) * inv_h);
                    float4 c = g_rgbpad4[rbase + (w0 + k + dx + PAD)];
                    accR[k] = fmaf(wgt, c.x, accR[k]);
                    accG[k] = fmaf(wgt, c.y, accG[k]);
                    accB[k] = fmaf(wgt, c.z, accB[k]);
                    accD[k] += wgt;
                }
                if (k < 7) Dk += a[k + 21] - a[k];
            }
        }
    };

#pragma unroll 1
    for (int p = 0; p < NPAIR; p++) {
        const int dx0 = 2 * p - PAD;
        const bool has1 = (2 * p + 1 < SW);
        float* cs0 = s_cs + ((p & 1) * 2 + 0) * (RSTRIP * PW);
        float* cs1 = s_cs + ((p & 1) * 2 + 1) * (RSTRIP * PW);

        if (colA) {
            phaseA(dx0, cs0);
            if (has1) phaseA(dx0 + 1, cs1);
        }
        __syncthreads();   // one barrier per pair; buffer parity protects reads of pair p-1

        if (outA) {
            phaseB(dx0, cs0);
            if (has1) phaseB(dx0 + 1, cs1);
        }
        // no trailing barrier: next pair writes the other two buffers
    }

    // ---- exclusive writeout of this (strip, group) slice ----
    if (outA) {
        const int g = blockIdx.y;
        int p = orow * IMW + w0;
        *(float4*)&g_acc[g][0][p]     = make_float4(accR[0], accR[1], accR[2], accR[3]);
        *(float4*)&g_acc[g][0][p + 4] = make_float4(accR[4], accR[5], accR[6], accR[7]);
        *(float4*)&g_acc[g][1][p]     = make_float4(accG[0], accG[1], accG[2], accG[3]);
        *(float4*)&g_acc[g][1][p + 4] = make_float4(accG[4], accG[5], accG[6], accG[7]);
        *(float4*)&g_acc[g][2][p]     = make_float4(accB[0], accB[1], accB[2], accB[3]);
        *(float4*)&g_acc[g][2][p + 4] = make_float4(accB[4], accB[5], accB[6], accB[7]);
        *(float4*)&g_acc[g][3][p]     = make_float4(accD[0], accD[1], accD[2], accD[3]);
        *(float4*)&g_acc[g][3][p + 4] = make_float4(accD[4], accD[5], accD[6], accD[7]);
    }
}

// -------- kernel 3: reduce the 21 dy-group partials, normalize, clip (4 px/thread) --------
__global__ void reduce_kernel(float* __restrict__ out) {
    int q = blockIdx.x * blockDim.x + threadIdx.x;   // float4 index
    if (q >= HW / 4) return;
    float4 nr = make_float4(0.f, 0.f, 0.f, 0.f);
    float4 ng = nr, nb = nr, dn = nr;
#pragma unroll
    for (int g = 0; g < NGROUP; g++) {
        float4 v;
        v = ((const float4*)g_acc[g][0])[q]; nr.x += v.x; nr.y += v.y; nr.z += v.z; nr.w += v.w;
        v = ((const float4*)g_acc[g][1])[q]; ng.x += v.x; ng.y += v.y; ng.z += v.z; ng.w += v.w;
        v = ((const float4*)g_acc[g][2])[q]; nb.x += v.x; nb.y += v.y; nb.z += v.z; nb.w += v.w;
        v = ((const float4*)g_acc[g][3])[q]; dn.x += v.x; dn.y += v.y; dn.z += v.z; dn.w += v.w;
    }
    float4 o0, o1, o2;
    o0.x = fminf(fmaxf(nr.x / dn.x, 0.f), 1.f);
    o0.y = fminf(fmaxf(nr.y / dn.y, 0.f), 1.f);
    o0.z = fminf(fmaxf(nr.z / dn.z, 0.f), 1.f);
    o0.w = fminf(fmaxf(nr.w / dn.w, 0.f), 1.f);
    o1.x = fminf(fmaxf(ng.x / dn.x, 0.f), 1.f);
    o1.y = fminf(fmaxf(ng.y / dn.y, 0.f), 1.f);
    o1.z = fminf(fmaxf(ng.z / dn.z, 0.f), 1.f);
    o1.w = fminf(fmaxf(ng.w / dn.w, 0.f), 1.f);
    o2.x = fminf(fmaxf(nb.x / dn.x, 0.f), 1.f);
    o2.y = fminf(fmaxf(nb.y / dn.y, 0.f), 1.f);
    o2.z = fminf(fmaxf(nb.z / dn.z, 0.f), 1.f);
    o2.w = fminf(fmaxf(nb.w / dn.w, 0.f), 1.f);
    ((float4*)out)[q]              = o0;
    ((float4*)(out + HW))[q]       = o1;
    ((float4*)(out + 2 * HW))[q]   = o2;
}

extern "C" void kernel_launch(void* const* d_in, const int* in_sizes, int n_in,
                              void* d_out, int out_size) {
    const float* rgb = (const float*)d_in[0];
    const float* hp  = (const float*)d_in[1];
    if (n_in >= 2 && in_sizes[0] == 1) {   // defensive input-order check
        rgb = (const float*)d_in[1];
        hp  = (const float*)d_in[0];
    }
    const int smem_bytes = (NROWS * PW + 4 * RSTRIP * PW) * sizeof(float);  // 66,240 B
    static bool attr_set = false;
    if (!attr_set) {
        cudaFuncSetAttribute(nlm_kernel, cudaFuncAttributeMaxDynamicSharedMemorySize, smem_bytes);
        attr_set = true;
    }
    prep_kernel<<<(PW * PW + 255) / 256, 256>>>(rgb);
    nlm_kernel<<<dim3(NSTRIP, NGROUP), NT, smem_bytes>>>(hp);
    reduce_kernel<<<(HW / 4 + 255) / 256, 256>>>((float*)d_out);
}